// round 2
// baseline (speedup 1.0000x reference)
#include <cuda_runtime.h>
#include <cstdint>
#include <cstddef>

#define DIM       256
#define TM        128
#define KT        16
#define NTHREADS  256
#define XS_STRIDE 260
#define WS_STRIDE 264
#define WS_BUF    (KT*WS_STRIDE)      /* 4224 floats per buffer */
#define NEG_SLOPE 0.01f

/* smem layout in floats */
#define XS_OFF 0
#define WS_OFF (TM*XS_STRIDE)                 /* 33280 */
#define B1_OFF (WS_OFF + 2*WS_BUF)            /* 41728 */
#define AUX_OFF (B1_OFF + 256)                /* 41984 */
#define SMEM_FLOATS (AUX_OFF + 256)           /* 42240 -> 168960 bytes */

/* ---------- packed f32x2 helpers (sm_100+ PTX) ---------- */
__device__ __forceinline__ unsigned long long pack2(float lo, float hi) {
    unsigned long long r;
    asm("mov.b64 %0, {%1, %2};" : "=l"(r) : "r"(__float_as_uint(lo)), "r"(__float_as_uint(hi)));
    return r;
}
__device__ __forceinline__ void unpack2(unsigned long long v, float& lo, float& hi) {
    unsigned int a, b;
    asm("mov.b64 {%0, %1}, %2;" : "=r"(a), "=r"(b) : "l"(v));
    lo = __uint_as_float(a); hi = __uint_as_float(b);
}
__device__ __forceinline__ void fma2(unsigned long long& acc, unsigned long long a, unsigned long long b) {
    asm("fma.rn.f32x2 %0, %1, %2, %0;" : "+l"(acc) : "l"(a), "l"(b));
}
__device__ __forceinline__ float lrelu(float x) {
    return fmaxf(x, 0.f) + NEG_SLOPE * fminf(x, 0.f);
}

/* ---------- weight tile staging: global [N][256] row-major -> smem [kk][n^swz] ---------- */
template<int ROUNDS>
__device__ __forceinline__ void ldg_wtile(float4* pre, const float* __restrict__ W,
                                          int k0, int nvalid, int tid) {
    int kq = tid & 3;
    int nb = tid >> 2;              /* 0..63 */
#pragma unroll
    for (int r = 0; r < ROUNDS; r++) {
        int n = nb + 64 * r;
        if (n < nvalid) pre[r] = *(const float4*)(W + (size_t)n * DIM + k0 + 4 * kq);
        else            pre[r] = make_float4(0.f, 0.f, 0.f, 0.f);
    }
}
template<int ROUNDS>
__device__ __forceinline__ void sts_wtile(float* Ws, const float4* pre, int tid) {
    int kq = tid & 3;
    int nb = tid >> 2;
#pragma unroll
    for (int r = 0; r < ROUNDS; r++) {
        int n = nb + 64 * r;
        const float* v = (const float*)&pre[r];
#pragma unroll
        for (int j = 0; j < 4; j++) {
            int kk = 4 * kq + j;
            int ph = n ^ (4 * (kk & 7));         /* bank swizzle */
            Ws[kk * WS_STRIDE + ph] = v[j];
        }
    }
}

/* ---------- inner GEMM tile: C[8m x (NJ*64?) ...] rows m0..m0+7, n = 4tx+64j+i ---------- */
template<int NJ>
__device__ __forceinline__ void gemm_tile(const float* __restrict__ Xs,
                                          const float* __restrict__ Ws,
                                          int m0, int tx, int t,
                                          unsigned long long (&acc)[4][NJ * 4]) {
#pragma unroll
    for (int kk = 0; kk < KT; kk++) {
        int k = t * KT + kk;
        float xf[8];
#pragma unroll
        for (int i = 0; i < 8; i++) xf[i] = Xs[(m0 + i) * XS_STRIDE + k];
        unsigned long long xp[4];
#pragma unroll
        for (int p = 0; p < 4; p++) xp[p] = pack2(xf[2 * p], xf[2 * p + 1]);
        int q = (4 * tx) ^ (4 * (kk & 7));
#pragma unroll
        for (int j = 0; j < NJ; j++) {
            float4 w = *(const float4*)(Ws + kk * WS_STRIDE + q + 64 * j);
            const float* wf = (const float*)&w;
#pragma unroll
            for (int i = 0; i < 4; i++) {
                unsigned long long bb = pack2(wf[i], wf[i]);
#pragma unroll
                for (int p = 0; p < 4; p++) fma2(acc[p][4 * j + i], xp[p], bb);
            }
        }
    }
}

/* ---------- gathered X load: 128 rows of 256 fp32 into Xs[m][k] ---------- */
__device__ __forceinline__ void gather_row(float* Xs, const float* __restrict__ atom,
                                           int m, int g, int q) {
    const float4* src = (const float4*)(atom + (size_t)g * DIM);
#pragma unroll
    for (int c = 0; c < 8; c++) {
        int k4 = c * 8 + q;
        *(float4*)&Xs[m * XS_STRIDE + 4 * k4] = src[k4];
    }
}

/* ================= STEM HEAD ================= */
__global__ void __launch_bounds__(NTHREADS, 1)
stems_kernel(const float* __restrict__ atom,
             const float* __restrict__ w1, const float* __restrict__ b1,
             const float* __restrict__ w2, const float* __restrict__ b2,
             const int* __restrict__ slices, const int* __restrict__ st_batch,
             const int* __restrict__ st_atom, float* __restrict__ out) {
    extern __shared__ float sm[];
    float* Xs  = sm + XS_OFF;
    float* Ws  = sm + WS_OFF;
    float* b1s = sm + B1_OFF;
    float* b2s = sm + AUX_OFF;
    int tid = threadIdx.x, blk = blockIdx.x;

    b1s[tid] = b1[tid];
    if (tid < 128) b2s[tid] = (tid < 105) ? b2[tid] : 0.f;

    { /* gather */
        int lane = tid & 31, warp = tid >> 5;
        int mrow = lane >> 3, q = lane & 7;
#pragma unroll
        for (int rr = 0; rr < 16; rr += 4) {
            int m  = warp * 16 + rr + mrow;
            int mg = blk * TM + m;
            int g  = slices[st_batch[mg]] + st_atom[mg];
            gather_row(Xs, atom, m, g, q);
        }
    }

    int tx = tid & 15, ty = tid >> 4;
    int m0 = ty * 8;

    float4 pre[4];
    ldg_wtile<4>(pre, w1, 0, 256, tid);
    sts_wtile<4>(Ws, pre, tid);
    __syncthreads();

    unsigned long long acc1[4][16];
#pragma unroll
    for (int j = 0; j < 4; j++)
#pragma unroll
        for (int i = 0; i < 4; i++) {
            float bv = b1s[4 * tx + 64 * j + i];
            unsigned long long pv = pack2(bv, bv);
#pragma unroll
            for (int p = 0; p < 4; p++) acc1[p][4 * j + i] = pv;
        }

#pragma unroll 1
    for (int t = 0; t < 16; t++) {
        if (t < 15) ldg_wtile<4>(pre, w1, (t + 1) * KT, 256, tid);
        gemm_tile<4>(Xs, Ws + (t & 1) * WS_BUF, m0, tx, t, acc1);
        if (t < 15) sts_wtile<4>(Ws + ((t + 1) & 1) * WS_BUF, pre, tid);
        __syncthreads();
    }

    /* H = LeakyReLU(acc1) overwrites Xs (all GEMM1 reads done: loop-final sync) */
#pragma unroll
    for (int p = 0; p < 4; p++)
#pragma unroll
        for (int j4 = 0; j4 < 16; j4++) {
            int n = 4 * tx + 64 * (j4 >> 2) + (j4 & 3);
            float lo, hi; unpack2(acc1[p][j4], lo, hi);
            Xs[(m0 + 2 * p)     * XS_STRIDE + n] = lrelu(lo);
            Xs[(m0 + 2 * p + 1) * XS_STRIDE + n] = lrelu(hi);
        }

    float4 pre2[2];
    ldg_wtile<2>(pre2, w2, 0, 105, tid);
    sts_wtile<2>(Ws, pre2, tid);
    __syncthreads();

    unsigned long long acc2[4][8];
#pragma unroll
    for (int j = 0; j < 2; j++)
#pragma unroll
        for (int i = 0; i < 4; i++) {
            float bv = b2s[4 * tx + 64 * j + i];
            unsigned long long pv = pack2(bv, bv);
#pragma unroll
            for (int p = 0; p < 4; p++) acc2[p][4 * j + i] = pv;
        }

#pragma unroll 1
    for (int t = 0; t < 16; t++) {
        if (t < 15) ldg_wtile<2>(pre2, w2, (t + 1) * KT, 105, tid);
        gemm_tile<2>(Xs, Ws + (t & 1) * WS_BUF, m0, tx, t, acc2);
        if (t < 15) sts_wtile<2>(Ws + ((t + 1) & 1) * WS_BUF, pre2, tid);
        __syncthreads();
    }

    size_t rbase = (size_t)blk * TM;
#pragma unroll
    for (int p = 0; p < 4; p++)
#pragma unroll
        for (int j4 = 0; j4 < 8; j4++) {
            int n = 4 * tx + 64 * (j4 >> 2) + (j4 & 3);
            if (n < 105) {
                float lo, hi; unpack2(acc2[p][j4], lo, hi);
                out[(rbase + m0 + 2 * p)     * 105 + n] = lo;
                out[(rbase + m0 + 2 * p + 1) * 105 + n] = hi;
            }
        }
}

/* ================= BOND HEAD ================= */
__global__ void __launch_bounds__(NTHREADS, 1)
bonds_kernel(const float* __restrict__ atom,
             const float* __restrict__ w1, const float* __restrict__ b1,
             const float* __restrict__ w2, const float* __restrict__ b2,
             const int* __restrict__ slices, const int* __restrict__ bd_batch,
             const int* __restrict__ bonds, float* __restrict__ out) {
    extern __shared__ float sm[];
    float* Xs  = sm + XS_OFF;
    float* Ws  = sm + WS_OFF;
    float* b1s = sm + B1_OFF;
    float* w2s = sm + AUX_OFF;
    int tid = threadIdx.x, blk = blockIdx.x;

    b1s[tid] = b1[tid];
    w2s[tid] = w2[tid];

    { /* gather: row r -> bond r/2 endpoint r%2 */
        int lane = tid & 31, warp = tid >> 5;
        int mrow = lane >> 3, q = lane & 7;
#pragma unroll
        for (int rr = 0; rr < 16; rr += 4) {
            int m  = warp * 16 + rr + mrow;
            int mg = blk * TM + m;
            int bd = mg >> 1, e = mg & 1;
            int g  = slices[bd_batch[bd]] + bonds[2 * bd + e];
            gather_row(Xs, atom, m, g, q);
        }
    }

    int tx = tid & 15, ty = tid >> 4;
    int m0 = ty * 8;

    float4 pre[4];
    ldg_wtile<4>(pre, w1, 0, 256, tid);
    sts_wtile<4>(Ws, pre, tid);
    __syncthreads();

    unsigned long long acc1[4][16];
#pragma unroll
    for (int j = 0; j < 4; j++)
#pragma unroll
        for (int i = 0; i < 4; i++) {
            float bv = b1s[4 * tx + 64 * j + i];
            unsigned long long pv = pack2(bv, bv);
#pragma unroll
            for (int p = 0; p < 4; p++) acc1[p][4 * j + i] = pv;
        }

#pragma unroll 1
    for (int t = 0; t < 16; t++) {
        if (t < 15) ldg_wtile<4>(pre, w1, (t + 1) * KT, 256, tid);
        gemm_tile<4>(Xs, Ws + (t & 1) * WS_BUF, m0, tx, t, acc1);
        if (t < 15) sts_wtile<4>(Ws + ((t + 1) & 1) * WS_BUF, pre, tid);
        __syncthreads();
    }

    /* second layer is a dot with w2: reduce in registers + half-warp shuffle */
    float yp[8];
#pragma unroll
    for (int i = 0; i < 8; i++) yp[i] = 0.f;
#pragma unroll
    for (int p = 0; p < 4; p++)
#pragma unroll
        for (int j4 = 0; j4 < 16; j4++) {
            int n = 4 * tx + 64 * (j4 >> 2) + (j4 & 3);
            float w = w2s[n];
            float lo, hi; unpack2(acc1[p][j4], lo, hi);
            yp[2 * p]     += lrelu(lo) * w;
            yp[2 * p + 1] += lrelu(hi) * w;
        }
#pragma unroll
    for (int off = 8; off >= 1; off >>= 1)
#pragma unroll
        for (int i = 0; i < 8; i++)
            yp[i] += __shfl_xor_sync(0xffffffffu, yp[i], off);

    if (tx == 0) {
        float b2v = b2[0];
        int bond0 = (blk * TM + m0) >> 1;     /* 4 bonds per 8 rows */
#pragma unroll
        for (int bnd = 0; bnd < 4; bnd++)
            out[bond0 + bnd] = 0.5f * (yp[2 * bnd] + yp[2 * bnd + 1]) + b2v;
    }
}

/* ================= launch ================= */
extern "C" void kernel_launch(void* const* d_in, const int* in_sizes, int n_in,
                              void* d_out, int out_size) {
    const float* atom = (const float*)d_in[0];
    const float* mol  = (const float*)d_in[1];
    const float* w_s1 = (const float*)d_in[2];
    const float* b_s1 = (const float*)d_in[3];
    const float* w_s2 = (const float*)d_in[4];
    const float* b_s2 = (const float*)d_in[5];
    const float* w_b1 = (const float*)d_in[6];
    const float* b_b1 = (const float*)d_in[7];
    const float* w_b2 = (const float*)d_in[8];
    const float* b_b2 = (const float*)d_in[9];
    const int* slices = (const int*)d_in[10];
    const int* st_b   = (const int*)d_in[11];
    const int* st_a   = (const int*)d_in[12];
    const int* bonds  = (const int*)d_in[13];
    const int* bd_b   = (const int*)d_in[14];

    int n_stems = in_sizes[11];
    int n_mol   = in_sizes[1];
    int n_bonds = in_sizes[14];

    float* out       = (float*)d_out;
    float* out_stem  = out;
    float* out_mol   = out + (size_t)n_stems * 105;
    float* out_bond  = out_mol + n_mol;

    size_t smem = (size_t)SMEM_FLOATS * sizeof(float);
    cudaFuncSetAttribute(stems_kernel, cudaFuncAttributeMaxDynamicSharedMemorySize, (int)smem);
    cudaFuncSetAttribute(bonds_kernel, cudaFuncAttributeMaxDynamicSharedMemorySize, (int)smem);

    cudaMemcpyAsync(out_mol, mol, (size_t)n_mol * sizeof(float), cudaMemcpyDeviceToDevice);

    bonds_kernel<<<(2 * n_bonds) / TM, NTHREADS, smem>>>(
        atom, w_b1, b_b1, w_b2, b_b2, slices, bd_b, bonds, out_bond);
    stems_kernel<<<n_stems / TM, NTHREADS, smem>>>(
        atom, w_s1, b_s1, w_s2, b_s2, slices, st_b, st_a, out_stem);
}

// round 4
// speedup vs baseline: 2.2342x; 2.2342x over previous
#include <cuda_runtime.h>
#include <cstdint>
#include <cstddef>

#define TPB 256
#define NEG_SLOPE 0.01f
#define XSTR 264                      /* bf16 units per X row (pad) */
#define WSTR 24                       /* bf16 units per W row (pad) */

/* smem byte offsets */
#define XHI_OFF 0
#define XLO_OFF (128 * XSTR * 2)                  /* 67584  */
#define WHI_OFF (2 * 128 * XSTR * 2)              /* 135168 */
#define WLO_OFF (WHI_OFF + 256 * WSTR * 2)        /* 147456 */
#define B1_OFF  (WLO_OFF + 256 * WSTR * 2)        /* 159744 */
#define W2_OFF  (B1_OFF + 1024)
#define GR_OFF  (W2_OFF + 1024)
#define SMEM_TOTAL (GR_OFF + 512)                 /* 162304 */

__device__ float g_H[(size_t)131072 * 256];

__device__ __forceinline__ float lrelu(float x) {
    return fmaxf(x, 0.f) + NEG_SLOPE * fminf(x, 0.f);
}
/* split (v0,v1) into packed bf16x2 hi and lo (v0 in low half) */
__device__ __forceinline__ void split2(float v0, float v1, uint32_t& h2, uint32_t& l2) {
    asm("cvt.rn.bf16x2.f32 %0, %1, %2;" : "=r"(h2) : "f"(v1), "f"(v0));
    float h0 = __uint_as_float(h2 << 16);
    float h1 = __uint_as_float(h2 & 0xffff0000u);
    asm("cvt.rn.bf16x2.f32 %0, %1, %2;" : "=r"(l2) : "f"(v1 - h1), "f"(v0 - h0));
}
__device__ __forceinline__ void mma16816(float* c, const uint32_t* a, uint32_t b0, uint32_t b1) {
    asm volatile(
        "mma.sync.aligned.m16n8k16.row.col.f32.bf16.bf16.f32 "
        "{%0,%1,%2,%3},{%4,%5,%6,%7},{%8,%9},{%0,%1,%2,%3};"
        : "+f"(c[0]), "+f"(c[1]), "+f"(c[2]), "+f"(c[3])
        : "r"(a[0]), "r"(a[1]), "r"(a[2]), "r"(a[3]), "r"(b0), "r"(b1));
}

/* W chunk (16 k-cols) global->regs and regs->split smem */
__device__ __forceinline__ void ldg_chunk(float4* pre, const float* __restrict__ W,
                                          int rows, int kc, int tid) {
    const float* p = W + (size_t)tid * 256 + kc * 16;
#pragma unroll
    for (int q = 0; q < 4; q++)
        pre[q] = (tid < rows) ? *(const float4*)(p + 4 * q) : make_float4(0.f, 0.f, 0.f, 0.f);
}
__device__ __forceinline__ void sts_chunk(char* sm, const float4* pre, int tid) {
    char* wh = sm + WHI_OFF + tid * (WSTR * 2);
    char* wl = sm + WLO_OFF + tid * (WSTR * 2);
#pragma unroll
    for (int q = 0; q < 4; q++) {
        uint32_t h0, h1, l0, l1;
        split2(pre[q].x, pre[q].y, h0, l0);
        split2(pre[q].z, pre[q].w, h1, l1);
        *(uint2*)(wh + q * 8) = make_uint2(h0, h1);
        *(uint2*)(wl + q * 8) = make_uint2(l0, l1);
    }
}

/* MODE 0: stems L1 (gather stems) -> g_H with bias+lrelu
   MODE 1: bonds head (gather bond endpoints) -> bond preds
   MODE 2: stems L2 (rows from g_H, W=w_s2 padded to 256 rows) -> stem preds */
template<int MODE>
__global__ void __launch_bounds__(TPB, 1)
mlp_kernel(const float* __restrict__ AsrcIn, const float* __restrict__ W1,
           const float* __restrict__ b1, const float* __restrict__ w2,
           const float* __restrict__ b2, const int* __restrict__ slices,
           const int* __restrict__ idxA, const int* __restrict__ idxB,
           float* __restrict__ outp) {
    constexpr int WROWS = (MODE == 2) ? 105 : 256;
    extern __shared__ char sm[];
    int tid = threadIdx.x, lid = tid & 31, wid = tid >> 5;
    int row_base = blockIdx.x * 128;

    int*   grow = (int*)(sm + GR_OFF);
    float* b1s  = (float*)(sm + B1_OFF);
    float* w2s  = (float*)(sm + W2_OFF);

    if (tid < 128) {
        int r = row_base + tid, g;
        if (MODE == 0)      g = slices[idxA[r]] + idxB[r];
        else if (MODE == 1) { int bd = r >> 1; g = slices[idxA[bd]] + idxB[2 * bd + (r & 1)]; }
        else                g = r;
        grow[tid] = g;
    }
    if (MODE == 2) b1s[tid] = (tid < 105) ? b2[tid] : 0.f;
    else           b1s[tid] = b1[tid];
    if (MODE == 1) w2s[tid] = w2[tid];
    __syncthreads();

    /* ---- X gather + bf16 split (each thread: half a row) ---- */
    {
        const float* Asrc = (MODE == 2) ? (const float*)g_H : AsrcIn;
        int row = tid >> 1, h = tid & 1;
        const float4* src = (const float4*)(Asrc + (size_t)grow[row] * 256 + h * 128);
        char* xh = sm + XHI_OFF + row * (XSTR * 2) + h * 256;
        char* xl = sm + XLO_OFF + row * (XSTR * 2) + h * 256;
#pragma unroll 8
        for (int q = 0; q < 32; q++) {
            float4 v = src[q];
            uint32_t h0, h1, l0, l1;
            split2(v.x, v.y, h0, l0);
            split2(v.z, v.w, h1, l1);
            *(uint2*)(xh + q * 8) = make_uint2(h0, h1);
            *(uint2*)(xl + q * 8) = make_uint2(l0, l1);
        }
    }

    float acc[4][8][4];
#pragma unroll
    for (int mt = 0; mt < 4; mt++)
#pragma unroll
        for (int nt = 0; nt < 8; nt++)
#pragma unroll
            for (int j = 0; j < 4; j++) acc[mt][nt][j] = 0.f;

    float4 pre[4];
    ldg_chunk(pre, W1, WROWS, 0, tid);
    sts_chunk(sm, pre, tid);
    __syncthreads();

    int wm = wid & 1, wn = wid >> 1;     /* warp grid 2m x 4n */
    int qr = lid >> 2, qc = lid & 3;

#pragma unroll 1
    for (int kc = 0; kc < 16; kc++) {
        if (kc < 15) ldg_chunk(pre, W1, WROWS, kc + 1, tid);

        uint32_t ah[4][4], al[4][4];
        {
            const char* xh = sm + XHI_OFF;
            const char* xl = sm + XLO_OFF;
            int kb = (kc * 16 + qc * 2) * 2;
#pragma unroll
            for (int mt = 0; mt < 4; mt++) {
                int r0 = (wm * 64 + mt * 16 + qr) * (XSTR * 2);
                int r1 = r0 + 8 * (XSTR * 2);
                ah[mt][0] = *(const uint32_t*)(xh + r0 + kb);
                ah[mt][1] = *(const uint32_t*)(xh + r1 + kb);
                ah[mt][2] = *(const uint32_t*)(xh + r0 + kb + 16);
                ah[mt][3] = *(const uint32_t*)(xh + r1 + kb + 16);
                al[mt][0] = *(const uint32_t*)(xl + r0 + kb);
                al[mt][1] = *(const uint32_t*)(xl + r1 + kb);
                al[mt][2] = *(const uint32_t*)(xl + r0 + kb + 16);
                al[mt][3] = *(const uint32_t*)(xl + r1 + kb + 16);
            }
        }
        {
            const char* wh = sm + WHI_OFF;
            const char* wl = sm + WLO_OFF;
            int kb = qc * 4;
#pragma unroll
            for (int nt = 0; nt < 8; nt++) {
                int c = (wn * 64 + nt * 8 + qr) * (WSTR * 2);
                uint32_t bh0 = *(const uint32_t*)(wh + c + kb);
                uint32_t bh1 = *(const uint32_t*)(wh + c + kb + 16);
                uint32_t bl0 = *(const uint32_t*)(wl + c + kb);
                uint32_t bl1 = *(const uint32_t*)(wl + c + kb + 16);
#pragma unroll
                for (int mt = 0; mt < 4; mt++) {
                    mma16816(acc[mt][nt], ah[mt], bh0, bh1);
                    mma16816(acc[mt][nt], al[mt], bh0, bh1);
                    mma16816(acc[mt][nt], ah[mt], bl0, bl1);
                }
            }
        }
        __syncthreads();
        if (kc < 15) { sts_chunk(sm, pre, tid); __syncthreads(); }
    }

    /* ================= epilogue ================= */
    if (MODE == 1) {
        float* ysm = (float*)(sm + WHI_OFF);   /* [4 wn][128 rows], W smem done */
#pragma unroll
        for (int mt = 0; mt < 4; mt++)
#pragma unroll
            for (int jr = 0; jr < 2; jr++) {
                float s = 0.f;
#pragma unroll
                for (int nt = 0; nt < 8; nt++) {
                    int c = wn * 64 + nt * 8 + 2 * qc;
                    s += lrelu(acc[mt][nt][2 * jr]     + b1s[c])     * w2s[c];
                    s += lrelu(acc[mt][nt][2 * jr + 1] + b1s[c + 1]) * w2s[c + 1];
                }
                s += __shfl_xor_sync(0xffffffffu, s, 1);
                s += __shfl_xor_sync(0xffffffffu, s, 2);
                if (qc == 0)
                    ysm[wn * 128 + wm * 64 + mt * 16 + qr + 8 * jr] = s;
            }
        __syncthreads();
        if (tid < 128) {
            float y = ysm[tid] + ysm[128 + tid] + ysm[256 + tid] + ysm[384 + tid];
            float y2 = __shfl_down_sync(0xffffffffu, y, 1);
            if (!(tid & 1))
                outp[(row_base + tid) >> 1] = 0.5f * (y + y2) + b2[0];
        }
    } else if (MODE == 0) {
#pragma unroll
        for (int mt = 0; mt < 4; mt++)
#pragma unroll
            for (int jr = 0; jr < 2; jr++) {
                size_t row = (size_t)row_base + wm * 64 + mt * 16 + qr + 8 * jr;
#pragma unroll
                for (int nt = 0; nt < 8; nt++) {
                    int c = wn * 64 + nt * 8 + 2 * qc;
                    float v0 = lrelu(acc[mt][nt][2 * jr]     + b1s[c]);
                    float v1 = lrelu(acc[mt][nt][2 * jr + 1] + b1s[c + 1]);
                    *(float2*)(g_H + row * 256 + c) = make_float2(v0, v1);
                }
            }
    } else { /* MODE 2 */
#pragma unroll
        for (int mt = 0; mt < 4; mt++)
#pragma unroll
            for (int jr = 0; jr < 2; jr++) {
                size_t row = (size_t)row_base + wm * 64 + mt * 16 + qr + 8 * jr;
#pragma unroll
                for (int nt = 0; nt < 8; nt++) {
                    int c = wn * 64 + nt * 8 + 2 * qc;
                    if (c < 105)
                        outp[row * 105 + c] = acc[mt][nt][2 * jr] + b1s[c];
                    if (c + 1 < 105)
                        outp[row * 105 + c + 1] = acc[mt][nt][2 * jr + 1] + b1s[c + 1];
                }
            }
    }
}

extern "C" void kernel_launch(void* const* d_in, const int* in_sizes, int n_in,
                              void* d_out, int out_size) {
    const float* atom = (const float*)d_in[0];
    const float* mol  = (const float*)d_in[1];
    const float* w_s1 = (const float*)d_in[2];
    const float* b_s1 = (const float*)d_in[3];
    const float* w_s2 = (const float*)d_in[4];
    const float* b_s2 = (const float*)d_in[5];
    const float* w_b1 = (const float*)d_in[6];
    const float* b_b1 = (const float*)d_in[7];
    const float* w_b2 = (const float*)d_in[8];
    const float* b_b2 = (const float*)d_in[9];
    const int* slices = (const int*)d_in[10];
    const int* st_b   = (const int*)d_in[11];
    const int* st_a   = (const int*)d_in[12];
    const int* bonds  = (const int*)d_in[13];
    const int* bd_b   = (const int*)d_in[14];

    int n_stems = in_sizes[11];
    int n_mol   = in_sizes[1];
    int n_bonds = in_sizes[14];

    float* out      = (float*)d_out;
    float* out_stem = out;
    float* out_mol  = out + (size_t)n_stems * 105;
    float* out_bond = out_mol + n_mol;

    cudaFuncSetAttribute(mlp_kernel<0>, cudaFuncAttributeMaxDynamicSharedMemorySize, SMEM_TOTAL);
    cudaFuncSetAttribute(mlp_kernel<1>, cudaFuncAttributeMaxDynamicSharedMemorySize, SMEM_TOTAL);
    cudaFuncSetAttribute(mlp_kernel<2>, cudaFuncAttributeMaxDynamicSharedMemorySize, SMEM_TOTAL);

    cudaMemcpyAsync(out_mol, mol, (size_t)n_mol * sizeof(float), cudaMemcpyDeviceToDevice);

    mlp_kernel<1><<<(2 * n_bonds) / 128, TPB, SMEM_TOTAL>>>(
        atom, w_b1, b_b1, w_b2, b_b2, slices, bd_b, bonds, out_bond);
    mlp_kernel<0><<<n_stems / 128, TPB, SMEM_TOTAL>>>(
        atom, w_s1, b_s1, nullptr, nullptr, slices, st_b, st_a, nullptr);
    mlp_kernel<2><<<n_stems / 128, TPB, SMEM_TOTAL>>>(
        nullptr, w_s2, nullptr, nullptr, b_s2, slices, nullptr, nullptr, out_stem);
}

// round 5
// speedup vs baseline: 2.2713x; 1.0166x over previous
#include <cuda_runtime.h>
#include <cstdint>
#include <cstddef>

#define TPB 256
#define NEG_SLOPE 0.01f
#define XSTRB 528                     /* X row stride bytes (264 bf16) */
#define WSTRB 48                      /* W row stride bytes (24 bf16)  */

/* smem byte offsets */
#define XHI_OFF 0
#define XLO_OFF 67584
#define WB_OFF  135168                /* 3 bufs x 24576 */
#define WBUF    24576
#define WLOD    12288                 /* lo region offset inside buf */
#define B1_OFF  208896
#define W2_OFF  209920
#define GR_OFF  210944
#define SMEM_TOTAL 211456

__device__ float g_H[(size_t)131072 * 256];
__device__ __align__(16) uint8_t g_Wsp[3 * 16 * 16384];   /* [which][kc][1024 chunks x 16B] */

__device__ __forceinline__ uint32_t smem_u32(const void* p) {
    uint32_t a;
    asm("{ .reg .u64 t; cvta.to.shared.u64 t, %1; cvt.u32.u64 %0, t; }" : "=r"(a) : "l"(p));
    return a;
}
__device__ __forceinline__ float lrelu(float x) {
    return fmaxf(x, 0.f) + NEG_SLOPE * fminf(x, 0.f);
}
__device__ __forceinline__ void split2(float v0, float v1, uint32_t& h2, uint32_t& l2) {
    asm("cvt.rn.bf16x2.f32 %0, %1, %2;" : "=r"(h2) : "f"(v1), "f"(v0));
    float h0 = __uint_as_float(h2 << 16);
    float h1 = __uint_as_float(h2 & 0xffff0000u);
    asm("cvt.rn.bf16x2.f32 %0, %1, %2;" : "=r"(l2) : "f"(v1 - h1), "f"(v0 - h0));
}
__device__ __forceinline__ void mma16816(float* c, const uint32_t* a, uint32_t b0, uint32_t b1) {
    asm volatile(
        "mma.sync.aligned.m16n8k16.row.col.f32.bf16.bf16.f32 "
        "{%0,%1,%2,%3},{%4,%5,%6,%7},{%8,%9},{%0,%1,%2,%3};"
        : "+f"(c[0]), "+f"(c[1]), "+f"(c[2]), "+f"(c[3])
        : "r"(a[0]), "r"(a[1]), "r"(a[2]), "r"(a[3]), "r"(b0), "r"(b1));
}
#define LDM_X4(r, a) \
    asm volatile("ldmatrix.sync.aligned.m8n8.x4.shared.b16 {%0,%1,%2,%3}, [%4];" \
        : "=r"((r)[0]), "=r"((r)[1]), "=r"((r)[2]), "=r"((r)[3]) : "r"(a))
#define CP16(dst, src) asm volatile("cp.async.cg.shared.global [%0], [%1], 16;" :: "r"(dst), "l"(src))
#define CP_COMMIT()    asm volatile("cp.async.commit_group;" ::: "memory")
#define CP_WAIT1()     asm volatile("cp.async.wait_group 1;" ::: "memory")

/* ---- prep: W[rows<=256][256] fp32 -> bf16 hi/lo chunks, fragment-friendly layout ---- */
__global__ void prep_split(const float* __restrict__ W, int which, int wrows) {
    int c = blockIdx.x * blockDim.x + threadIdx.x;   /* 0..16383 */
    int kc = c >> 10, j = c & 1023;
    int jj = j & 511, n = jj >> 1, kh = jj & 1;
    const float* src = W + (size_t)n * 256 + kc * 16 + kh * 8;
    float v[8];
#pragma unroll
    for (int q = 0; q < 8; q++) v[q] = (n < wrows) ? src[q] : 0.f;
    uint32_t h[4], l[4];
#pragma unroll
    for (int q = 0; q < 4; q++) split2(v[2 * q], v[2 * q + 1], h[q], l[q]);
    uint4 out = (j < 512) ? make_uint4(h[0], h[1], h[2], h[3])
                          : make_uint4(l[0], l[1], l[2], l[3]);
    *(uint4*)(g_Wsp + ((size_t)which * 16 + kc) * 16384 + (size_t)j * 16) = out;
}

__device__ __forceinline__ void issue_w(uint32_t sb, const uint8_t* wsrc, int kc, int tid) {
    if (kc <= 15) {
        uint32_t buf = sb + WB_OFF + (kc % 3) * WBUF;
        const uint8_t* src = wsrc + (size_t)kc * 16384 + (size_t)tid * 16;
#pragma unroll
        for (int i = 0; i < 4; i++) {
            int j = tid + 256 * i;
            uint32_t dst = buf + ((j >> 9) ? WLOD : 0) + ((j & 511) >> 1) * WSTRB + (j & 1) * 16;
            CP16(dst, src + i * 4096);
        }
    }
    CP_COMMIT();
}

/* MODE 0: stems L1 -> g_H (bias+lrelu) | MODE 1: bonds head | MODE 2: stems L2 from g_H */
template<int MODE>
__global__ void __launch_bounds__(TPB, 1)
mlp_kernel(const float* __restrict__ AsrcIn,
           const float* __restrict__ b1, const float* __restrict__ w2,
           const float* __restrict__ b2, const int* __restrict__ slices,
           const int* __restrict__ idxA, const int* __restrict__ idxB,
           float* __restrict__ outp) {
    constexpr int WIDX = (MODE == 0) ? 1 : (MODE == 1) ? 0 : 2;
    extern __shared__ char sm[];
    uint32_t sb = smem_u32(sm);
    int tid = threadIdx.x, lid = tid & 31, wid = tid >> 5;
    int row_base = blockIdx.x * 128;
    const uint8_t* wsrc = g_Wsp + (size_t)WIDX * 262144;

    int*   grow = (int*)(sm + GR_OFF);
    float* b1s  = (float*)(sm + B1_OFF);
    float* w2s  = (float*)(sm + W2_OFF);

    if (tid < 128) {
        int r = row_base + tid, g;
        if (MODE == 0)      g = slices[idxA[r]] + idxB[r];
        else if (MODE == 1) { int bd = r >> 1; g = slices[idxA[bd]] + idxB[2 * bd + (r & 1)]; }
        else                g = r;
        grow[tid] = g;
    }
    if (MODE == 2) b1s[tid] = (tid < 105) ? b2[tid] : 0.f;
    else           b1s[tid] = b1[tid];
    if (MODE == 1) w2s[tid] = w2[tid];
    __syncthreads();

    issue_w(sb, wsrc, 0, tid);
    issue_w(sb, wsrc, 1, tid);

    /* ---- X gather + bf16 split (each thread: half a row) ---- */
    {
        const float* Asrc = (MODE == 2) ? (const float*)g_H : AsrcIn;
        int row = tid >> 1, h = tid & 1;
        const float4* src = (const float4*)(Asrc + (size_t)grow[row] * 256 + h * 128);
        char* xh = sm + XHI_OFF + row * XSTRB + h * 256;
        char* xl = sm + XLO_OFF + row * XSTRB + h * 256;
#pragma unroll 8
        for (int q = 0; q < 32; q++) {
            float4 v = src[q];
            uint32_t h0, h1, l0, l1;
            split2(v.x, v.y, h0, l0);
            split2(v.z, v.w, h1, l1);
            *(uint2*)(xh + q * 8) = make_uint2(h0, h1);
            *(uint2*)(xl + q * 8) = make_uint2(l0, l1);
        }
    }

    float acc[4][8][4];
#pragma unroll
    for (int mt = 0; mt < 4; mt++)
#pragma unroll
        for (int nt = 0; nt < 8; nt++)
#pragma unroll
            for (int j = 0; j < 4; j++) acc[mt][nt][j] = 0.f;

    int wm = wid & 1, wn = wid >> 1;
    int qr = lid >> 2, qc = lid & 3;

    /* per-lane ldmatrix base addresses */
    uint32_t xa[4], wa[4];
#pragma unroll
    for (int mt = 0; mt < 4; mt++)
        xa[mt] = sb + XHI_OFF + (uint32_t)(wm * 64 + mt * 16 + (lid & 15)) * XSTRB + ((lid >> 4) << 4);
#pragma unroll
    for (int np = 0; np < 4; np++)
        wa[np] = (uint32_t)(wn * 64 + np * 16 + (lid & 7) + ((lid >> 4) << 3)) * WSTRB + (((lid >> 3) & 1) << 4);

#pragma unroll 1
    for (int kc = 0; kc < 16; kc++) {
        CP_WAIT1();
        __syncthreads();
        issue_w(sb, wsrc, kc + 2, tid);

        uint32_t ah[4][4], al[4][4];
#pragma unroll
        for (int mt = 0; mt < 4; mt++) {
            uint32_t a = xa[mt] + kc * 32;
            LDM_X4(ah[mt], a);
            LDM_X4(al[mt], a + (XLO_OFF - XHI_OFF));
        }
        uint32_t bb = sb + WB_OFF + (kc % 3) * WBUF;
#pragma unroll
        for (int np = 0; np < 4; np++) {
            uint32_t bh[4], bl[4];
            LDM_X4(bh, bb + wa[np]);
            LDM_X4(bl, bb + wa[np] + WLOD);
#pragma unroll
            for (int mt = 0; mt < 4; mt++) {
                mma16816(acc[mt][2 * np],     ah[mt], bh[0], bh[1]);
                mma16816(acc[mt][2 * np],     al[mt], bh[0], bh[1]);
                mma16816(acc[mt][2 * np],     ah[mt], bl[0], bl[1]);
                mma16816(acc[mt][2 * np + 1], ah[mt], bh[2], bh[3]);
                mma16816(acc[mt][2 * np + 1], al[mt], bh[2], bh[3]);
                mma16816(acc[mt][2 * np + 1], ah[mt], bl[2], bl[3]);
            }
        }
    }

    /* ================= epilogue ================= */
    if (MODE == 1) {
        __syncthreads();
        float* ysm = (float*)(sm + WB_OFF);   /* [4 wn][128 rows] */
#pragma unroll
        for (int mt = 0; mt < 4; mt++)
#pragma unroll
            for (int jr = 0; jr < 2; jr++) {
                float s = 0.f;
#pragma unroll
                for (int nt = 0; nt < 8; nt++) {
                    int c = wn * 64 + nt * 8 + 2 * qc;
                    s += lrelu(acc[mt][nt][2 * jr]     + b1s[c])     * w2s[c];
                    s += lrelu(acc[mt][nt][2 * jr + 1] + b1s[c + 1]) * w2s[c + 1];
                }
                s += __shfl_xor_sync(0xffffffffu, s, 1);
                s += __shfl_xor_sync(0xffffffffu, s, 2);
                if (qc == 0)
                    ysm[wn * 128 + wm * 64 + mt * 16 + qr + 8 * jr] = s;
            }
        __syncthreads();
        if (tid < 128) {
            float y = ysm[tid] + ysm[128 + tid] + ysm[256 + tid] + ysm[384 + tid];
            float y2 = __shfl_down_sync(0xffffffffu, y, 1);
            if (!(tid & 1))
                outp[(row_base + tid) >> 1] = 0.5f * (y + y2) + b2[0];
        }
    } else if (MODE == 0) {
#pragma unroll
        for (int mt = 0; mt < 4; mt++)
#pragma unroll
            for (int jr = 0; jr < 2; jr++) {
                size_t row = (size_t)row_base + wm * 64 + mt * 16 + qr + 8 * jr;
#pragma unroll
                for (int nt = 0; nt < 8; nt++) {
                    int c = wn * 64 + nt * 8 + 2 * qc;
                    float v0 = lrelu(acc[mt][nt][2 * jr]     + b1s[c]);
                    float v1 = lrelu(acc[mt][nt][2 * jr + 1] + b1s[c + 1]);
                    *(float2*)(g_H + row * 256 + c) = make_float2(v0, v1);
                }
            }
    } else { /* MODE 2 */
#pragma unroll
        for (int mt = 0; mt < 4; mt++)
#pragma unroll
            for (int jr = 0; jr < 2; jr++) {
                size_t row = (size_t)row_base + wm * 64 + mt * 16 + qr + 8 * jr;
#pragma unroll
                for (int nt = 0; nt < 8; nt++) {
                    int c = wn * 64 + nt * 8 + 2 * qc;
                    if (c < 105)
                        outp[row * 105 + c] = acc[mt][nt][2 * jr] + b1s[c];
                    if (c + 1 < 105)
                        outp[row * 105 + c + 1] = acc[mt][nt][2 * jr + 1] + b1s[c + 1];
                }
            }
    }
}

extern "C" void kernel_launch(void* const* d_in, const int* in_sizes, int n_in,
                              void* d_out, int out_size) {
    const float* atom = (const float*)d_in[0];
    const float* mol  = (const float*)d_in[1];
    const float* w_s1 = (const float*)d_in[2];
    const float* b_s1 = (const float*)d_in[3];
    const float* w_s2 = (const float*)d_in[4];
    const float* b_s2 = (const float*)d_in[5];
    const float* w_b1 = (const float*)d_in[6];
    const float* b_b1 = (const float*)d_in[7];
    const float* w_b2 = (const float*)d_in[8];
    const float* b_b2 = (const float*)d_in[9];
    const int* slices = (const int*)d_in[10];
    const int* st_b   = (const int*)d_in[11];
    const int* st_a   = (const int*)d_in[12];
    const int* bonds  = (const int*)d_in[13];
    const int* bd_b   = (const int*)d_in[14];

    int n_stems = in_sizes[11];
    int n_mol   = in_sizes[1];
    int n_bonds = in_sizes[14];

    float* out      = (float*)d_out;
    float* out_stem = out;
    float* out_mol  = out + (size_t)n_stems * 105;
    float* out_bond = out_mol + n_mol;

    cudaFuncSetAttribute(mlp_kernel<0>, cudaFuncAttributeMaxDynamicSharedMemorySize, SMEM_TOTAL);
    cudaFuncSetAttribute(mlp_kernel<1>, cudaFuncAttributeMaxDynamicSharedMemorySize, SMEM_TOTAL);
    cudaFuncSetAttribute(mlp_kernel<2>, cudaFuncAttributeMaxDynamicSharedMemorySize, SMEM_TOTAL);

    cudaMemcpyAsync(out_mol, mol, (size_t)n_mol * sizeof(float), cudaMemcpyDeviceToDevice);

    prep_split<<<64, 256>>>(w_b1, 0, 256);
    prep_split<<<64, 256>>>(w_s1, 1, 256);
    prep_split<<<64, 256>>>(w_s2, 2, 105);

    mlp_kernel<1><<<(2 * n_bonds) / 128, TPB, SMEM_TOTAL>>>(
        atom, b_b1, w_b2, b_b2, slices, bd_b, bonds, out_bond);
    mlp_kernel<0><<<n_stems / 128, TPB, SMEM_TOTAL>>>(
        atom, b_s1, nullptr, nullptr, slices, st_b, st_a, nullptr);
    mlp_kernel<2><<<n_stems / 128, TPB, SMEM_TOTAL>>>(
        nullptr, nullptr, nullptr, b_s2, slices, nullptr, nullptr, out_stem);
}